// round 16
// baseline (speedup 1.0000x reference)
#include <cuda_runtime.h>
#include <cuda_fp16.h>
#include <stdint.h>

#define TPB 256

// ---------------- smem layout (bytes) ----------------
// h tile (128 rows = 4 branches x 32 pos, 256B/row), double-buffered: 32 KB each
#define T_BUF(b)   ((b) * 32768)
// Phase-A chunk buffers alias the same region: [32 rows][128B] = 4 KB each
#define PA_BUF(b)  ((b) * 4096)
#define OFF_BASE  65536     // base fp16 [32 pos][65 uint32 stride] = 8320 B
#define OFF_SB0   73856
#define OFF_SB1   74368
#define OFF_SB2   74880
#define OFF_SP    75392
#define OFF_SQ    75904
#define OFF_SB3   76416     // 64 B
#define OFF_LUT   76480     // 648*4 = 2592
#define OFF_YRED  79072     // [128][17] fp32 = 8704
#define SMEM_BYTES 88064

// activation pre-scale (keeps branch-3 h1 within fp16 range)
#define ASCL   0.0625f
#define ASCL_I 16.0f

// ---------------- device images ----------------
// Zero-padded input: [8 ch][9 a1][9 a2][34 h][34 w]
__device__ __align__(16) float gInpP[749088];
// fp16 B-fragments packed as uint4 covering a PAIR of n-blocks:
//   entry = (kblk * npStride + npair) * 32 + lane,  lane = (n&7)*4 + ((k>>1)&3)
//   halves within entry: [((n>>3)&1)*4 + ((k>>3)&1)*2 + (k&1)]
__device__ __align__(16) __half gW0[90112];  // 704 x 128 (44 kblk x 8 npairs)
__device__ __align__(16) __half gW1[16384];  // 128 x 128 (8 x 8)
__device__ __align__(16) __half gW2[16384];
__device__ __align__(16) __half gW3[2048];   // 128 x 16 (8 x 1)

// ---------------- asm helpers ----------------
__device__ __forceinline__ uint32_t smem_u32(const void* p) {
    uint32_t a;
    asm("{ .reg .u64 t; cvta.to.shared.u64 t, %1; cvt.u32.u64 %0, t; }" : "=r"(a) : "l"(p));
    return a;
}
__device__ __forceinline__ void ldmx4(uint32_t r[4], uint32_t addr) {
    asm volatile("ldmatrix.sync.aligned.m8n8.x4.shared.b16 {%0,%1,%2,%3}, [%4];"
        : "=r"(r[0]), "=r"(r[1]), "=r"(r[2]), "=r"(r[3]) : "r"(addr));
}
__device__ __forceinline__ void mma16816(float* d, const uint32_t* a, uint32_t b0, uint32_t b1) {
    asm volatile("mma.sync.aligned.m16n8k16.row.col.f32.f16.f16.f32 "
        "{%0,%1,%2,%3}, {%4,%5,%6,%7}, {%8,%9}, {%0,%1,%2,%3};"
        : "+f"(d[0]), "+f"(d[1]), "+f"(d[2]), "+f"(d[3])
        : "r"(a[0]), "r"(a[1]), "r"(a[2]), "r"(a[3]), "r"(b0), "r"(b1));
}
__device__ __forceinline__ uint32_t packh2(float v0, float v1) {
    __half2 h = __floats2half2_rn(v0, v1);
    return *(uint32_t*)&h;
}
__device__ __forceinline__ float2 unpackh2(uint32_t u) {
    return __half22float2(*(__half2*)&u);
}

// GEMM: A (fp16) from swizzled smem via ldmatrix, B uint4 (n-pair) frags from global.
// Warp computes rows [mrow, mrow+16*MT) x cols [npair0*16, (npair0+NT/2)*16).
template<int KS, int MT, int NT, int RLOG>
__device__ __forceinline__ void gemm_gb4(uint32_t aBuf,
    const uint4* __restrict__ gB,
    int kblk0, int npStride, int npair0, int mrow, float* acc, int lane)
{
    const int rA = mrow + (lane & 15);
    const int selA = lane >> 4;
    const uint32_t aRow = aBuf + (rA << RLOG);
    const int xorA = rA & 7;
    const uint4* b = gB + (kblk0 * npStride + npair0) * 32 + lane;
#pragma unroll
    for (int ks = 0; ks < KS; ks++) {
        const uint32_t offA = ((uint32_t)(((ks * 2 + selA) ^ xorA))) << 4;
        uint32_t ah[MT][4];
#pragma unroll
        for (int mt = 0; mt < MT; mt++)
            ldmx4(ah[mt], aRow + (mt << (RLOG + 4)) + offA);
        uint4 bv[NT / 2];
#pragma unroll
        for (int np = 0; np < NT / 2; np++) bv[np] = b[np * 32];
        b += npStride * 32;
#pragma unroll
        for (int np = 0; np < NT / 2; np++)
#pragma unroll
            for (int mt = 0; mt < MT; mt++) {
                mma16816(acc + (mt * NT + np * 2 + 0) * 4, ah[mt], bv[np].x, bv[np].y);
                mma16816(acc + (mt * NT + np * 2 + 1) * 4, ah[mt], bv[np].z, bv[np].w);
            }
    }
}

// ---------------- prep kernel: padded input + fp16 B-frag (n-pair uint4) weights ----------------
__device__ __forceinline__ void pack_frag(__half* dst, float v, int k, int n, int npStride) {
    int entry = ((k >> 4) * npStride + (n >> 4)) * 32 + (n & 7) * 4 + ((k >> 1) & 3);
    int sub = ((n >> 3) & 1) * 4 + ((k >> 3) & 1) * 2 + (k & 1);
    dst[entry * 8 + sub] = __float2half_rn(v);
}

__global__ void prep_kernel(const float* __restrict__ inp,
                            const float* __restrict__ W0, const float* __restrict__ W1,
                            const float* __restrict__ W2, const float* __restrict__ W3) {
    int idx = blockIdx.x * 256 + threadIdx.x;
    const int nP = 749088, n0 = 90112, n1 = 16384, n2 = 16384, n3 = 2048;
    if (idx < nP) {
        int w1 = idx % 34, h1 = (idx / 34) % 34;
        int a2 = (idx / 1156) % 9, a1 = (idx / 10404) % 9, ch = idx / 93636;
        bool ok = (a1 >= 1 && a1 <= 7 && a2 >= 1 && a2 <= 7 &&
                   h1 >= 1 && h1 <= 32 && w1 >= 1 && w1 <= 32);
        gInpP[idx] = ok ? inp[ch * 50176 + (a1 - 1) * 7168 + (a2 - 1) * 1024
                              + (h1 - 1) * 32 + (w1 - 1)] : 0.f;
    } else if (idx < nP + n0) {
        int r = idx - nP, k = r >> 7, n = r & 127;
        float v = (k < 648) ? W0[k * 128 + n] : 0.f;
        pack_frag(gW0, v, k, n, 8);
    } else if (idx < nP + n0 + n1) {
        int r = idx - nP - n0, k = r >> 7, n = r & 127;
        pack_frag(gW1, W1[k * 128 + n], k, n, 8);
    } else if (idx < nP + n0 + n1 + n2) {
        int r = idx - nP - n0 - n1, k = r >> 7, n = r & 127;
        pack_frag(gW2, W2[k * 128 + n], k, n, 8);
    } else if (idx < nP + n0 + n1 + n2 + n3) {
        int r = idx - nP - n0 - n1 - n2, k = r >> 4, n = r & 15;
        float v = (n < 12) ? W3[k * 12 + n] : 0.f;
        pack_frag(gW3, v, k, n, 1);
    }
}

// ---------------- main kernel ----------------
__global__ __launch_bounds__(TPB, 2)
void inr_hmma_kernel(const float* __restrict__ W0,
                     const float* __restrict__ b0g, const float* __restrict__ b1g,
                     const float* __restrict__ b2g, const float* __restrict__ b3g,
                     float* __restrict__ outp) {
    extern __shared__ char sm[];
    const uint32_t sbase = smem_u32(sm);
    const int tid = threadIdx.x;
    const int lane = tid & 31, w = tid >> 5;

    const int blk = blockIdx.x;
    const int ablk = blk >> 5, hgrp = blk & 31;   // 32 positions = 1 h-row x 32 w
    const int ahi = ablk / 7, awi = ablk % 7;

    uint32_t* sBase32 = (uint32_t*)(sm + OFF_BASE);   // [32 pos][65] packed fp16 pairs
    float* sb0 = (float*)(sm + OFF_SB0);
    float* sb1 = (float*)(sm + OFF_SB1);
    float* sb2 = (float*)(sm + OFF_SB2);
    float* sP  = (float*)(sm + OFF_SP);
    float* sQ  = (float*)(sm + OFF_SQ);
    float* sb3 = (float*)(sm + OFF_SB3);
    int*   lut = (int*)(sm + OFF_LUT);
    float* yred = (float*)(sm + OFF_YRED);            // [128][17]

    for (int c = tid; c < 128; c += TPB) {
        sb0[c] = b0g[c]; sb1[c] = b1g[c]; sb2[c] = b2g[c];
        sP[c] = W0[716 * 128 + c] + W0[717 * 128 + c];
        sQ[c] = W0[718 * 128 + c] + W0[719 * 128 + c];
    }
    if (tid < 12) sb3[tid] = b3g[tid];
    for (int k = tid; k < 648; k += TPB) {
        int aj = k % 3, ai = (k / 3) % 3, kj = (k / 9) % 3, ki = (k / 27) % 3, ch = k / 81;
        lut[k] = ch * 93636 + ai * 10404 + aj * 1156 + ki * 34 + kj;
    }
    __syncthreads();

    const uint4* gw0 = (const uint4*)gW0;
    const uint4* gw1 = (const uint4*)gW1;
    const uint4* gw2 = (const uint4*)gW2;
    const uint4* gw3 = (const uint4*)gW3;

    const int rq  = lane >> 2;          // 0..7
    const int nqp = (lane & 3) * 2;     // 0,2,4,6

    // ================= Phase A: base = q_feat @ W0 (11 chunks of K=64) =================
    // 8 warps: 2 m-groups (16 rows) x 4 n-groups (32 cols)
    const int mgA = w >> 2, ngA = w & 3;

    float accA[16];
#pragma unroll
    for (int i = 0; i < 16; i++) accA[i] = 0.f;

    const int gm = tid & 31;          // gather: position
    const int gstrip = tid >> 5;      // gather: k-pair strip (0..7)
    const int ibase = ahi * 10404 + awi * 1156 + hgrp * 34 + gm;

    auto gather = [&](int c, bool check) {
        char* dh = sm + PA_BUF(c & 1);
#pragma unroll
        for (int q = 0; q < 4; q++) {
            int kp = gstrip * 4 + q;
            int kk = c * 64 + kp * 2;
            float v0, v1;
            if (!check) {
                v0 = gInpP[ibase + lut[kk]];
                v1 = gInpP[ibase + lut[kk + 1]];
            } else {
                v0 = (kk < 648) ? gInpP[ibase + lut[kk]] : 0.f;
                v1 = (kk + 1 < 648) ? gInpP[ibase + lut[kk + 1]] : 0.f;
            }
            int off = gm * 128 + ((((kp >> 2) ^ (gm & 7)) << 4)) + (kp & 3) * 4;
            *(uint32_t*)(dh + off) = packh2(v0, v1);
        }
    };

    gather(0, false);
    __syncthreads();
    for (int c = 0; c < 11; c++) {
        if (c < 10) gather(c + 1, c + 1 == 10);
        gemm_gb4<4, 1, 4, 7>(sbase + PA_BUF(c & 1), gw0,
                             c * 4, 8, ngA * 2, mgA * 16, accA, lane);
        __syncthreads();
    }

    // park base as packed fp16 in smem, stride 65 uint32 (bank-spread)
#pragma unroll
    for (int nt = 0; nt < 4; nt++) {
        int n = ngA * 32 + nt * 8 + nqp;
        int p0 = mgA * 16 + rq;
        sBase32[p0 * 65 + (n >> 1)]       = packh2(accA[nt * 4 + 0], accA[nt * 4 + 1]);
        sBase32[(p0 + 8) * 65 + (n >> 1)] = packh2(accA[nt * 4 + 2], accA[nt * 4 + 3]);
    }
    __syncthreads();

    // ================= batched branch phase: M = 128 rows = 4 branches x 32 pos ========
    // ---- h1 epi: each warp fills rows w*16..w*16+15, all 128 cols, into T_BUF(0) ----
#pragma unroll
    for (int half = 0; half < 2; half++) {
        int r = w * 16 + rq + half * 8;
        int pos = r & 31, br = r >> 5;
        float powv = __uint_as_float((uint32_t)(127 + 5 * (br + 1)) << 23);
        float s = (hgrp == 0 && pos < 4) ? (pos < 2 ? 0.0625f : (2.f / 7.f)) : 1.f;
#pragma unroll
        for (int nt = 0; nt < 16; nt++) {
            int n = nt * 8 + nqp;
            float2 bv = unpackh2(sBase32[pos * 65 + (n >> 1)]);
            float e0 = fmaf(powv, sP[n], sQ[n]);
            float e1 = fmaf(powv, sP[n + 1], sQ[n + 1]);
            float v0 = fmaxf(bv.x + sb0[n] + s * e0, 0.f) * ASCL;
            float v1 = fmaxf(bv.y + sb0[n + 1] + s * e1, 0.f) * ASCL;
            int off = (r << 8) + ((((n >> 3) ^ (r & 7)) << 4)) + (n & 7) * 2;
            *(uint32_t*)(sm + T_BUF(0) + off) = packh2(v0, v1);
        }
    }
    __syncthreads();

    // branch GEMM warp tiling: 2 m-groups (64 rows) x 4 n-groups (32 cols)
    const int mg = w >> 2, ng = w & 3;

    // ---- W1: M=128 GEMM, h2 -> T_BUF(1) ----
    {
        float acc[64];
#pragma unroll
        for (int i = 0; i < 64; i++) acc[i] = 0.f;
        gemm_gb4<8, 4, 4, 8>(sbase + T_BUF(0), gw1, 0, 8, ng * 2, mg * 64, acc, lane);
#pragma unroll
        for (int mt = 0; mt < 4; mt++)
#pragma unroll
            for (int nt = 0; nt < 4; nt++) {
                int n = ng * 32 + nt * 8 + nqp;
                float bb0 = sb1[n], bb1 = sb1[n + 1];
                const float* a = acc + (mt * 4 + nt) * 4;
#pragma unroll
                for (int half = 0; half < 2; half++) {
                    int r = mg * 64 + mt * 16 + rq + half * 8;
                    float v0 = fmaxf(ASCL_I * a[half * 2 + 0] + bb0, 0.f) * ASCL;
                    float v1 = fmaxf(ASCL_I * a[half * 2 + 1] + bb1, 0.f) * ASCL;
                    int off = (r << 8) + ((((n >> 3) ^ (r & 7)) << 4)) + (n & 7) * 2;
                    *(uint32_t*)(sm + T_BUF(1) + off) = packh2(v0, v1);
                }
            }
    }
    __syncthreads();

    // ---- W2: M=128 GEMM, h3 -> T_BUF(0) ----
    {
        float acc[64];
#pragma unroll
        for (int i = 0; i < 64; i++) acc[i] = 0.f;
        gemm_gb4<8, 4, 4, 8>(sbase + T_BUF(1), gw2, 0, 8, ng * 2, mg * 64, acc, lane);
#pragma unroll
        for (int mt = 0; mt < 4; mt++)
#pragma unroll
            for (int nt = 0; nt < 4; nt++) {
                int n = ng * 32 + nt * 8 + nqp;
                float bb0 = sb2[n], bb1 = sb2[n + 1];
                const float* a = acc + (mt * 4 + nt) * 4;
#pragma unroll
                for (int half = 0; half < 2; half++) {
                    int r = mg * 64 + mt * 16 + rq + half * 8;
                    float v0 = fmaxf(ASCL_I * a[half * 2 + 0] + bb0, 0.f) * ASCL;
                    float v1 = fmaxf(ASCL_I * a[half * 2 + 1] + bb1, 0.f) * ASCL;
                    int off = (r << 8) + ((((n >> 3) ^ (r & 7)) << 4)) + (n & 7) * 2;
                    *(uint32_t*)(sm + T_BUF(0) + off) = packh2(v0, v1);
                }
            }
    }
    __syncthreads();

    // ---- W3 (N=16): warps with ng<2, warp tile m64 x n8 ----
    if (ng < 2) {
        float y[16];
#pragma unroll
        for (int i = 0; i < 16; i++) y[i] = 0.f;
        const int rA = mg * 64 + (lane & 15);
        const int selA = lane >> 4;
        const uint32_t aRow = sbase + T_BUF(0) + (rA << 8);
        const int xorA = rA & 7;
#pragma unroll
        for (int ks = 0; ks < 8; ks++) {
            const uint32_t offA = ((uint32_t)(((ks * 2 + selA) ^ xorA))) << 4;
            uint32_t ah[4][4];
#pragma unroll
            for (int mt = 0; mt < 4; mt++)
                ldmx4(ah[mt], aRow + mt * 4096 + offA);
            uint4 bv = gw3[ks * 32 + lane];
            uint32_t b0 = ng ? bv.z : bv.x;
            uint32_t b1 = ng ? bv.w : bv.y;
#pragma unroll
            for (int mt = 0; mt < 4; mt++)
                mma16816(y + mt * 4, ah[mt], b0, b1);
        }
        // park to yred [128][17]
#pragma unroll
        for (int mt = 0; mt < 4; mt++)
#pragma unroll
            for (int half = 0; half < 2; half++)
#pragma unroll
                for (int j = 0; j < 2; j++) {
                    int n = ng * 8 + nqp + j;
                    int r = mg * 64 + mt * 16 + rq + half * 8;
                    yred[r * 17 + n] = y[mt * 4 + half * 2 + j];
                }
    }
    __syncthreads();

    // ---- cross-branch reduce + scatter: out = 4 * sum_br y + b3 ----
    for (int e = tid; e < 384; e += TPB) {
        int pos = e / 12, n = e % 12;
        float sum = yred[pos * 17 + n] + yred[(32 + pos) * 17 + n]
                  + yred[(64 + pos) * 17 + n] + yred[(96 + pos) * 17 + n];
        float val = 4.0f * sum + sb3[n];
        int rgb = n >> 2, pr = (n >> 1) & 1, qc = n & 1;
        outp[rgb * 200704 + ahi * 28672 + awi * 4096 +
             (2 * hgrp + pr) * 64 + (2 * pos + qc)] = val;
    }
}

extern "C" void kernel_launch(void* const* d_in, const int* in_sizes, int n_in,
                              void* d_out, int out_size) {
    (void)in_sizes; (void)n_in; (void)out_size;
    const float* inp = (const float*)d_in[0];
    const float* W0  = (const float*)d_in[1];
    const float* b0  = (const float*)d_in[2];
    const float* W1  = (const float*)d_in[3];
    const float* b1  = (const float*)d_in[4];
    const float* W2  = (const float*)d_in[5];
    const float* b2  = (const float*)d_in[6];
    const float* W3  = (const float*)d_in[7];
    const float* b3  = (const float*)d_in[8];
    float* outp = (float*)d_out;

    const int prep_tasks = 749088 + 90112 + 16384 + 16384 + 2048;
    prep_kernel<<<(prep_tasks + 255) / 256, 256>>>(inp, W0, W1, W2, W3);

    cudaFuncSetAttribute(inr_hmma_kernel, cudaFuncAttributeMaxDynamicSharedMemorySize, SMEM_BYTES);
    inr_hmma_kernel<<<1568, TPB, SMEM_BYTES>>>(W0, b0, b1, b2, b3, outp);
}

// round 17
// speedup vs baseline: 1.0674x; 1.0674x over previous
#include <cuda_runtime.h>
#include <cuda_fp16.h>
#include <stdint.h>

// activation pre-scale (keeps branch-3 h1 within fp16 range)
#define ASCL   0.0625f
#define ASCL_I 16.0f

// ---------------- device images ----------------
__device__ __align__(16) float gInpP[749088];     // padded input [8][9][9][34][34]
__device__ __align__(16) __half gBase[6422528];   // base fp16 [1568 blk][32 pos][128]
// fp16 B-fragments packed as uint4 covering a PAIR of n-blocks:
//   entry = (kblk * npStride + npair) * 32 + lane,  lane = (n&7)*4 + ((k>>1)&3)
//   halves: [((n>>3)&1)*4 + ((k>>3)&1)*2 + (k&1)]
__device__ __align__(16) __half gW0[90112];  // 704 x 128 (44 kblk x 8 npairs)
__device__ __align__(16) __half gW1[16384];  // 128 x 128 (8 x 8)
__device__ __align__(16) __half gW2[16384];
__device__ __align__(16) __half gW3[2048];   // 128 x 16 (8 x 1)

// ---------------- asm helpers ----------------
__device__ __forceinline__ uint32_t smem_u32(const void* p) {
    uint32_t a;
    asm("{ .reg .u64 t; cvta.to.shared.u64 t, %1; cvt.u32.u64 %0, t; }" : "=r"(a) : "l"(p));
    return a;
}
__device__ __forceinline__ void ldmx4(uint32_t r[4], uint32_t addr) {
    asm volatile("ldmatrix.sync.aligned.m8n8.x4.shared.b16 {%0,%1,%2,%3}, [%4];"
        : "=r"(r[0]), "=r"(r[1]), "=r"(r[2]), "=r"(r[3]) : "r"(addr));
}
__device__ __forceinline__ void mma16816(float* d, const uint32_t* a, uint32_t b0, uint32_t b1) {
    asm volatile("mma.sync.aligned.m16n8k16.row.col.f32.f16.f16.f32 "
        "{%0,%1,%2,%3}, {%4,%5,%6,%7}, {%8,%9}, {%0,%1,%2,%3};"
        : "+f"(d[0]), "+f"(d[1]), "+f"(d[2]), "+f"(d[3])
        : "r"(a[0]), "r"(a[1]), "r"(a[2]), "r"(a[3]), "r"(b0), "r"(b1));
}
__device__ __forceinline__ uint32_t packh2(float v0, float v1) {
    __half2 h = __floats2half2_rn(v0, v1);
    return *(uint32_t*)&h;
}
__device__ __forceinline__ float2 unpackh2(uint32_t u) {
    return __half22float2(*(__half2*)&u);
}

// GEMM: A (fp16) from swizzled smem via ldmatrix, B uint4 (n-pair) frags from global.
template<int KS, int MT, int NT, int RLOG>
__device__ __forceinline__ void gemm_gb4(uint32_t aBuf,
    const uint4* __restrict__ gB,
    int kblk0, int npStride, int npair0, float* acc, int lane)
{
    const int rA = lane & 15;
    const int selA = lane >> 4;
    const uint32_t aRow = aBuf + (rA << RLOG);
    const int xorA = rA & 7;
    const uint4* b = gB + (kblk0 * npStride + npair0) * 32 + lane;
#pragma unroll
    for (int ks = 0; ks < KS; ks++) {
        const uint32_t offA = ((uint32_t)(((ks * 2 + selA) ^ xorA))) << 4;
        uint32_t ah[MT][4];
#pragma unroll
        for (int mt = 0; mt < MT; mt++)
            ldmx4(ah[mt], aRow + (mt << (RLOG + 4)) + offA);
        uint4 bv[NT / 2];
#pragma unroll
        for (int np = 0; np < NT / 2; np++) bv[np] = b[np * 32];
        b += npStride * 32;
#pragma unroll
        for (int np = 0; np < NT / 2; np++)
#pragma unroll
            for (int mt = 0; mt < MT; mt++) {
                mma16816(acc + (mt * NT + np * 2 + 0) * 4, ah[mt], bv[np].x, bv[np].y);
                mma16816(acc + (mt * NT + np * 2 + 1) * 4, ah[mt], bv[np].z, bv[np].w);
            }
    }
}

// ---------------- prep kernel ----------------
__device__ __forceinline__ void pack_frag(__half* dst, float v, int k, int n, int npStride) {
    int entry = ((k >> 4) * npStride + (n >> 4)) * 32 + (n & 7) * 4 + ((k >> 1) & 3);
    int sub = ((n >> 3) & 1) * 4 + ((k >> 3) & 1) * 2 + (k & 1);
    dst[entry * 8 + sub] = __float2half_rn(v);
}

__global__ void prep_kernel(const float* __restrict__ inp,
                            const float* __restrict__ W0, const float* __restrict__ W1,
                            const float* __restrict__ W2, const float* __restrict__ W3) {
    int idx = blockIdx.x * 256 + threadIdx.x;
    const int nP = 749088, n0 = 90112, n1 = 16384, n2 = 16384, n3 = 2048;
    if (idx < nP) {
        int w1 = idx % 34, h1 = (idx / 34) % 34;
        int a2 = (idx / 1156) % 9, a1 = (idx / 10404) % 9, ch = idx / 93636;
        bool ok = (a1 >= 1 && a1 <= 7 && a2 >= 1 && a2 <= 7 &&
                   h1 >= 1 && h1 <= 32 && w1 >= 1 && w1 <= 32);
        gInpP[idx] = ok ? inp[ch * 50176 + (a1 - 1) * 7168 + (a2 - 1) * 1024
                              + (h1 - 1) * 32 + (w1 - 1)] : 0.f;
    } else if (idx < nP + n0) {
        int r = idx - nP, k = r >> 7, n = r & 127;
        float v = (k < 648) ? W0[k * 128 + n] : 0.f;
        pack_frag(gW0, v, k, n, 8);
    } else if (idx < nP + n0 + n1) {
        int r = idx - nP - n0, k = r >> 7, n = r & 127;
        pack_frag(gW1, W1[k * 128 + n], k, n, 8);
    } else if (idx < nP + n0 + n1 + n2) {
        int r = idx - nP - n0 - n1, k = r >> 7, n = r & 127;
        pack_frag(gW2, W2[k * 128 + n], k, n, 8);
    } else if (idx < nP + n0 + n1 + n2 + n3) {
        int r = idx - nP - n0 - n1 - n2, k = r >> 4, n = r & 15;
        float v = (n < 12) ? W3[k * 12 + n] : 0.f;
        pack_frag(gW3, v, k, n, 1);
    }
}

// ================= KERNEL A: base = q_feat @ W0, fp16 -> gBase =================
#define A_PABUF(b) ((b) * 4096)
#define A_LUT      8192
#define A_SMEM     11264

__global__ __launch_bounds__(128, 4)
void phaseA_kernel(float* dummy) {
    extern __shared__ char sm[];
    const uint32_t sbase = smem_u32(sm);
    const int tid = threadIdx.x;
    const int lane = tid & 31, w = tid >> 5;
    const int ng = w;

    const int blk = blockIdx.x;
    const int ablk = blk >> 5, hgrp = blk & 31;
    const int ahi = ablk / 7, awi = ablk % 7;

    int* lut = (int*)(sm + A_LUT);
    for (int k = tid; k < 648; k += 128) {
        int aj = k % 3, ai = (k / 3) % 3, kj = (k / 9) % 3, ki = (k / 27) % 3, ch = k / 81;
        lut[k] = ch * 93636 + ai * 10404 + aj * 1156 + ki * 34 + kj;
    }
    __syncthreads();

    const uint4* gw0 = (const uint4*)gW0;

    float base_[32];
#pragma unroll
    for (int i = 0; i < 32; i++) base_[i] = 0.f;

    const int gm = tid & 31;
    const int gstrip = tid >> 5;
    const int ibase = ahi * 10404 + awi * 1156 + hgrp * 34 + gm;

    auto gather = [&](int c, bool check) {
        char* dh = sm + A_PABUF(c & 1);
#pragma unroll
        for (int q = 0; q < 8; q++) {
            int kp = gstrip * 8 + q;
            int kk = c * 64 + kp * 2;
            float v0, v1;
            if (!check) {
                v0 = gInpP[ibase + lut[kk]];
                v1 = gInpP[ibase + lut[kk + 1]];
            } else {
                v0 = (kk < 648) ? gInpP[ibase + lut[kk]] : 0.f;
                v1 = (kk + 1 < 648) ? gInpP[ibase + lut[kk + 1]] : 0.f;
            }
            int off = gm * 128 + ((((kp >> 2) ^ (gm & 7)) << 4)) + (kp & 3) * 4;
            *(uint32_t*)(dh + off) = packh2(v0, v1);
        }
    };

    gather(0, false);
    __syncthreads();
    for (int c = 0; c < 11; c++) {
        if (c < 10) gather(c + 1, c + 1 == 10);
        gemm_gb4<4, 2, 4, 7>(sbase + A_PABUF(c & 1), gw0,
                             c * 4, 8, ng * 2, base_, lane);
        __syncthreads();
    }

    // store base fp16 to global
    const int rq = lane >> 2, nqp = (lane & 3) * 2;
    __half* gb = gBase + (size_t)blk * 4096;
#pragma unroll
    for (int mt = 0; mt < 2; mt++)
#pragma unroll
        for (int nt = 0; nt < 4; nt++) {
            int n = ng * 32 + nt * 8 + nqp;
            const float* a = base_ + (mt * 4 + nt) * 4;
#pragma unroll
            for (int half = 0; half < 2; half++) {
                int r = mt * 16 + rq + half * 8;
                *(uint32_t*)&gb[r * 128 + n] = packh2(a[half * 2 + 0], a[half * 2 + 1]);
            }
        }
    (void)dummy;
}

// ================= KERNEL B: 4 branches from gBase =================
#define B_TBUF(b) ((b) * 8192)
#define B_BASE    16384      // [32 pos][65 uint32] = 8320
#define B_SB0     24704
#define B_SB1     25216
#define B_SB2     25728
#define B_SP      26240
#define B_SQ      26752
#define B_SB3     27264      // 64
#define B_SMEM    27648

__global__ __launch_bounds__(128, 5)
void branch_kernel(const float* __restrict__ W0,
                   const float* __restrict__ b0g, const float* __restrict__ b1g,
                   const float* __restrict__ b2g, const float* __restrict__ b3g,
                   float* __restrict__ outp) {
    extern __shared__ char sm[];
    const uint32_t sbase = smem_u32(sm);
    const int tid = threadIdx.x;
    const int lane = tid & 31, w = tid >> 5;
    const int ng = w;

    const int blk = blockIdx.x;
    const int ablk = blk >> 5, hgrp = blk & 31;
    const int ahi = ablk / 7, awi = ablk % 7;

    uint32_t* sBase32 = (uint32_t*)(sm + B_BASE);
    float* sb0 = (float*)(sm + B_SB0);
    float* sb1 = (float*)(sm + B_SB1);
    float* sb2 = (float*)(sm + B_SB2);
    float* sP  = (float*)(sm + B_SP);
    float* sQ  = (float*)(sm + B_SQ);
    float* sb3 = (float*)(sm + B_SB3);

    for (int c = tid; c < 128; c += 128) {
        sb0[c] = b0g[c]; sb1[c] = b1g[c]; sb2[c] = b2g[c];
        sP[c] = W0[716 * 128 + c] + W0[717 * 128 + c];
        sQ[c] = W0[718 * 128 + c] + W0[719 * 128 + c];
    }
    if (tid < 12) sb3[tid] = b3g[tid];
    // copy base into smem (stride-65 uint32)
    {
        const uint32_t* gb32 = (const uint32_t*)(gBase + (size_t)blk * 4096);
#pragma unroll
        for (int t = 0; t < 16; t++) {
            int e = tid + t * 128;
            sBase32[(e >> 6) * 65 + (e & 63)] = gb32[e];
        }
    }
    __syncthreads();

    const uint4* gw1 = (const uint4*)gW1;
    const uint4* gw2 = (const uint4*)gW2;
    const uint4* gw3 = (const uint4*)gW3;

    const int rq = lane >> 2, nqp = (lane & 3) * 2;

    float y[8];
#pragma unroll
    for (int i = 0; i < 8; i++) y[i] = 0.f;
    float powv = 32.f;
    int p = 0;

    for (int br = 0; br < 4; br++) {
        // ---- h1 = relu(base + b0 + s*(powv*P + Q)) * ASCL -> T_BUF(p) ----
#pragma unroll
        for (int mt = 0; mt < 2; mt++) {
#pragma unroll
            for (int nt = 0; nt < 4; nt++) {
                int n = ng * 32 + nt * 8 + nqp;
                float e0 = fmaf(powv, sP[n], sQ[n]);
                float e1 = fmaf(powv, sP[n + 1], sQ[n + 1]);
                float bb0 = sb0[n], bb1 = sb0[n + 1];
#pragma unroll
                for (int half = 0; half < 2; half++) {
                    int r = mt * 16 + rq + half * 8;
                    float s = 1.f;
                    if (hgrp == 0 && r < 4) s = (r < 2) ? 0.0625f : (2.f / 7.f);
                    float2 bv = unpackh2(sBase32[r * 65 + (n >> 1)]);
                    float v0 = fmaxf(bv.x + bb0 + s * e0, 0.f) * ASCL;
                    float v1 = fmaxf(bv.y + bb1 + s * e1, 0.f) * ASCL;
                    int off = (r << 8) + ((((n >> 3) ^ (r & 7)) << 4)) + (n & 7) * 2;
                    *(uint32_t*)(sm + B_TBUF(p) + off) = packh2(v0, v1);
                }
            }
        }
        __syncthreads();

        float acc[32];
#pragma unroll
        for (int i = 0; i < 32; i++) acc[i] = 0.f;
        gemm_gb4<8, 2, 4, 8>(sbase + B_TBUF(p), gw1, 0, 8, ng * 2, acc, lane);
        // h2 -> buf p^1
#pragma unroll
        for (int mt = 0; mt < 2; mt++)
#pragma unroll
            for (int nt = 0; nt < 4; nt++) {
                int n = ng * 32 + nt * 8 + nqp;
                float bb0 = sb1[n], bb1 = sb1[n + 1];
                const float* a = acc + (mt * 4 + nt) * 4;
#pragma unroll
                for (int half = 0; half < 2; half++) {
                    int r = mt * 16 + rq + half * 8;
                    float v0 = fmaxf(ASCL_I * a[half * 2 + 0] + bb0, 0.f) * ASCL;
                    float v1 = fmaxf(ASCL_I * a[half * 2 + 1] + bb1, 0.f) * ASCL;
                    int off = (r << 8) + ((((n >> 3) ^ (r & 7)) << 4)) + (n & 7) * 2;
                    *(uint32_t*)(sm + B_TBUF(p ^ 1) + off) = packh2(v0, v1);
                }
            }
        __syncthreads();

#pragma unroll
        for (int i = 0; i < 32; i++) acc[i] = 0.f;
        gemm_gb4<8, 2, 4, 8>(sbase + B_TBUF(p ^ 1), gw2, 0, 8, ng * 2, acc, lane);
        // h3 -> buf p
#pragma unroll
        for (int mt = 0; mt < 2; mt++)
#pragma unroll
            for (int nt = 0; nt < 4; nt++) {
                int n = ng * 32 + nt * 8 + nqp;
                float bb0 = sb2[n], bb1 = sb2[n + 1];
                const float* a = acc + (mt * 4 + nt) * 4;
#pragma unroll
                for (int half = 0; half < 2; half++) {
                    int r = mt * 16 + rq + half * 8;
                    float v0 = fmaxf(ASCL_I * a[half * 2 + 0] + bb0, 0.f) * ASCL;
                    float v1 = fmaxf(ASCL_I * a[half * 2 + 1] + bb1, 0.f) * ASCL;
                    int off = (r << 8) + ((((n >> 3) ^ (r & 7)) << 4)) + (n & 7) * 2;
                    *(uint32_t*)(sm + B_TBUF(p) + off) = packh2(v0, v1);
                }
            }
        __syncthreads();

        // y += (h3/16) @ W3: warps ng<2, each uses its half of the n-pair uint4
        if (ng < 2) {
            const int rA = lane & 15;
            const int selA = lane >> 4;
            const uint32_t aRow = sbase + B_TBUF(p) + (rA << 8);
            const int xorA = rA & 7;
#pragma unroll
            for (int ks = 0; ks < 8; ks++) {
                const uint32_t offA = ((uint32_t)(((ks * 2 + selA) ^ xorA))) << 4;
                uint32_t ah[2][4];
                ldmx4(ah[0], aRow + offA);
                ldmx4(ah[1], aRow + 4096 + offA);
                uint4 bv = gw3[ks * 32 + lane];
                uint32_t b0 = ng ? bv.z : bv.x;
                uint32_t b1 = ng ? bv.w : bv.y;
                mma16816(y + 0, ah[0], b0, b1);
                mma16816(y + 4, ah[1], b0, b1);
            }
        }
        p ^= 1;
        powv *= 32.f;
    }

    // ---- scatter (pixel shuffle); out = 4*y_scaled*... = 4*16*ASCL*... -> 4*y + b3 ----
    if (ng < 2) {
#pragma unroll
        for (int mt = 0; mt < 2; mt++)
#pragma unroll
            for (int half = 0; half < 2; half++)
#pragma unroll
                for (int j = 0; j < 2; j++) {
                    int n = ng * 8 + nqp + j;
                    if (n < 12) {
                        int r = mt * 16 + rq + half * 8;
                        float val = 4.0f * y[mt * 4 + half * 2 + j] + sb3[n];
                        int rgb = n >> 2, pr = (n >> 1) & 1, qc = n & 1;
                        outp[rgb * 200704 + ahi * 28672 + awi * 4096 +
                             (2 * hgrp + pr) * 64 + (2 * r + qc)] = val;
                    }
                }
    }
}

extern "C" void kernel_launch(void* const* d_in, const int* in_sizes, int n_in,
                              void* d_out, int out_size) {
    (void)in_sizes; (void)n_in; (void)out_size;
    const float* inp = (const float*)d_in[0];
    const float* W0  = (const float*)d_in[1];
    const float* b0  = (const float*)d_in[2];
    const float* W1  = (const float*)d_in[3];
    const float* b1  = (const float*)d_in[4];
    const float* W2  = (const float*)d_in[5];
    const float* b2  = (const float*)d_in[6];
    const float* W3  = (const float*)d_in[7];
    const float* b3  = (const float*)d_in[8];
    float* outp = (float*)d_out;

    const int prep_tasks = 749088 + 90112 + 16384 + 16384 + 2048;
    prep_kernel<<<(prep_tasks + 255) / 256, 256>>>(inp, W0, W1, W2, W3);

    cudaFuncSetAttribute(phaseA_kernel, cudaFuncAttributeMaxDynamicSharedMemorySize, A_SMEM);
    phaseA_kernel<<<1568, 128, A_SMEM>>>(outp);

    cudaFuncSetAttribute(branch_kernel, cudaFuncAttributeMaxDynamicSharedMemorySize, B_SMEM);
    branch_kernel<<<1568, 128, B_SMEM>>>(W0, b0, b1, b2, b3, outp);
}